// round 11
// baseline (speedup 1.0000x reference)
#include <cuda_runtime.h>
#include <cuda_bf16.h>
#include <cstdint>

// V[b,n,f,t] = sum_p cos(obs[b,p,f,t] - tpd[b,p,n,f])
// 4-mic square degeneracy: pairs[3]==pairs[2], pairs[5]==-pairs[0] ->
// rank-8 contraction over 4 distinct phase groups (rep pairs 0,1,2,4).
//
// Round-11: TMA bulk stores. Compute identical to round-4 (best timed), but
// results are staged in a smem tile V[36][300] f32 and written to GMEM with
// 36 x cp.async.bulk.global.shared::cta (1200 B each) -- the 44 MB output
// stream bypasses the per-SM L1 global-store data path entirely.

#define NP    6
#define NG    4
#define NDIR  36
#define NF    257
#define NT    300
#define NB    4
#define NTQ   75           // t-quads
#define NH    2            // n-halves
#define NPH   18           // n per half

__global__ __launch_bounds__(160)
void dirfeat_kernel(const float* __restrict__ obs,     // (B*P, F, T)
                    const float* __restrict__ azi,     // (B, N)
                    const float* __restrict__ ele,     // (B, N)
                    const float* __restrict__ pairs,   // (P, 3)
                    const float* __restrict__ freq,    // (F,)
                    float* __restrict__ out)           // (B, N, F, T)
{
    const int b  = blockIdx.x / NF;
    const int f  = blockIdx.x - b * NF;
    const int tid = threadIdx.x;

    // cs[n][2g] = cos(tau_g), cs[n][2g+1] = sin(tau_g)
    __shared__ __align__(16) float cs[NDIR][2 * NG];
    // Output staging tile: V[n][t], rows contiguous 1200 B for bulk copy
    __shared__ __align__(16) float Vs[NDIR][NT];

    // ---- Phase 1: 144 steering entries ----
    if (tid < NDIR * NG) {
        const int n = tid >> 2;
        const int g = tid & 3;
        const int rep = (g == 3) ? 4 : g;   // rep pair indices {0,1,2,4}

        const float a  = azi[b * NDIR + n];
        const float el = ele[b * NDIR + n];
        float sa, ca, se, ce;
        __sincosf(a,  &sa, &ca);
        __sincosf(el, &se, &ce);
        const float rx = se * ca, ry = se * sa, rz = ce;
        const float dot = pairs[rep * 3 + 0] * rx
                        + pairs[rep * 3 + 1] * ry
                        + pairs[rep * 3 + 2] * rz;
        const float tau = (6.283185307179586f / 343.0f) * dot * freq[f];
        float s, c;
        __sincosf(tau, &s, &c);
        cs[n][2 * g]     = c;
        cs[n][2 * g + 1] = s;
    }
    __syncthreads();

    // ---- Phase 2: threads 0..149 -> (n-half, t-quad); write to smem ----
    if (tid < NH * NTQ) {
        const int h  = (tid >= NTQ) ? 1 : 0;
        const int tq = tid - h * NTQ;
        const int t0 = tq * 4;

        const unsigned pstr = NF * NT;                 // 77100
        const float* ob = obs + (unsigned)((b * NP) * NF + f) * NT + t0;

        float uc[NG][4], us[NG][4];

        {   // group 0: pairs 0 and 5 (negated vector -> sin difference)
            const float4 oA = *reinterpret_cast<const float4*>(ob);
            const float4 oB = *reinterpret_cast<const float4*>(ob + 5 * pstr);
            float sA, cA, sB, cB;
            __sincosf(oA.x, &sA, &cA); __sincosf(oB.x, &sB, &cB);
            uc[0][0] = cA + cB; us[0][0] = sA - sB;
            __sincosf(oA.y, &sA, &cA); __sincosf(oB.y, &sB, &cB);
            uc[0][1] = cA + cB; us[0][1] = sA - sB;
            __sincosf(oA.z, &sA, &cA); __sincosf(oB.z, &sB, &cB);
            uc[0][2] = cA + cB; us[0][2] = sA - sB;
            __sincosf(oA.w, &sA, &cA); __sincosf(oB.w, &sB, &cB);
            uc[0][3] = cA + cB; us[0][3] = sA - sB;
        }
        {   // group 2: pairs 2 and 3 (identical vector -> sum)
            const float4 oA = *reinterpret_cast<const float4*>(ob + 2 * pstr);
            const float4 oB = *reinterpret_cast<const float4*>(ob + 3 * pstr);
            float sA, cA, sB, cB;
            __sincosf(oA.x, &sA, &cA); __sincosf(oB.x, &sB, &cB);
            uc[2][0] = cA + cB; us[2][0] = sA + sB;
            __sincosf(oA.y, &sA, &cA); __sincosf(oB.y, &sB, &cB);
            uc[2][1] = cA + cB; us[2][1] = sA + sB;
            __sincosf(oA.z, &sA, &cA); __sincosf(oB.z, &sB, &cB);
            uc[2][2] = cA + cB; us[2][2] = sA + sB;
            __sincosf(oA.w, &sA, &cA); __sincosf(oB.w, &sB, &cB);
            uc[2][3] = cA + cB; us[2][3] = sA + sB;
        }
        {   // group 1: pair 1 alone
            const float4 o = *reinterpret_cast<const float4*>(ob + 1 * pstr);
            __sincosf(o.x, &us[1][0], &uc[1][0]);
            __sincosf(o.y, &us[1][1], &uc[1][1]);
            __sincosf(o.z, &us[1][2], &uc[1][2]);
            __sincosf(o.w, &us[1][3], &uc[1][3]);
        }
        {   // group 3: pair 4 alone
            const float4 o = *reinterpret_cast<const float4*>(ob + 4 * pstr);
            __sincosf(o.x, &us[3][0], &uc[3][0]);
            __sincosf(o.y, &us[3][1], &uc[3][1]);
            __sincosf(o.z, &us[3][2], &uc[3][2]);
            __sincosf(o.w, &us[3][3], &uc[3][3]);
        }

        const float4* cp = reinterpret_cast<const float4*>(&cs[h * NPH][0]);

#pragma unroll
        for (int i = 0; i < NPH; i++) {
            const float4 w0 = cp[2 * i];       // c0 s0 c1 s1
            const float4 w1 = cp[2 * i + 1];   // c2 s2 c3 s3

            float a0, a1, a2, a3;
            a0 = uc[0][0] * w0.x;               a1 = uc[0][1] * w0.x;
            a2 = uc[0][2] * w0.x;               a3 = uc[0][3] * w0.x;
            a0 = fmaf(us[0][0], w0.y, a0);      a1 = fmaf(us[0][1], w0.y, a1);
            a2 = fmaf(us[0][2], w0.y, a2);      a3 = fmaf(us[0][3], w0.y, a3);
            a0 = fmaf(uc[1][0], w0.z, a0);      a1 = fmaf(uc[1][1], w0.z, a1);
            a2 = fmaf(uc[1][2], w0.z, a2);      a3 = fmaf(uc[1][3], w0.z, a3);
            a0 = fmaf(us[1][0], w0.w, a0);      a1 = fmaf(us[1][1], w0.w, a1);
            a2 = fmaf(us[1][2], w0.w, a2);      a3 = fmaf(us[1][3], w0.w, a3);
            a0 = fmaf(uc[2][0], w1.x, a0);      a1 = fmaf(uc[2][1], w1.x, a1);
            a2 = fmaf(uc[2][2], w1.x, a2);      a3 = fmaf(uc[2][3], w1.x, a3);
            a0 = fmaf(us[2][0], w1.y, a0);      a1 = fmaf(us[2][1], w1.y, a1);
            a2 = fmaf(us[2][2], w1.y, a2);      a3 = fmaf(us[2][3], w1.y, a3);
            a0 = fmaf(uc[3][0], w1.z, a0);      a1 = fmaf(uc[3][1], w1.z, a1);
            a2 = fmaf(uc[3][2], w1.z, a2);      a3 = fmaf(uc[3][3], w1.z, a3);
            a0 = fmaf(us[3][0], w1.w, a0);      a1 = fmaf(us[3][1], w1.w, a1);
            a2 = fmaf(us[3][2], w1.w, a2);      a3 = fmaf(us[3][3], w1.w, a3);

            *reinterpret_cast<float4*>(&Vs[h * NPH + i][t0]) =
                make_float4(a0, a1, a2, a3);
        }
    }
    __syncthreads();

    // ---- Phase 3: 36 TMA bulk stores (1200 B per n-row) ----
    if (tid < NDIR) {
        asm volatile("fence.proxy.async.shared::cta;" ::: "memory");
        uint32_t src;
        asm("{ .reg .u64 t; cvta.to.shared.u64 t, %1; cvt.u32.u64 %0, t; }"
            : "=r"(src) : "l"(&Vs[tid][0]));
        float* dst = out + ((size_t)((b * NDIR + tid) * NF) + f) * NT;
        asm volatile(
            "cp.async.bulk.global.shared::cta.bulk_group [%0], [%1], %2;"
            :: "l"(dst), "r"(src), "r"(NT * 4) : "memory");
        asm volatile("cp.async.bulk.commit_group;" ::: "memory");
        asm volatile("cp.async.bulk.wait_group 0;" ::: "memory");
    }
}

extern "C" void kernel_launch(void* const* d_in, const int* in_sizes, int n_in,
                              void* d_out, int out_size) {
    const float* obs   = (const float*)d_in[0];
    const float* azi   = (const float*)d_in[1];
    const float* ele   = (const float*)d_in[2];
    const float* pairs = (const float*)d_in[3];
    const float* freq  = (const float*)d_in[4];
    float* out = (float*)d_out;

    dim3 grid(NB * NF);   // 1028 blocks: one per (b,f)
    dim3 block(160);      // 5 warps; 150 compute, 36 issue TMA stores
    dirfeat_kernel<<<grid, block>>>(obs, azi, ele, pairs, freq, out);
}

// round 12
// speedup vs baseline: 1.2922x; 1.2922x over previous
#include <cuda_runtime.h>
#include <cuda_bf16.h>

// V[b,n,f,t] = sum_p cos(obs[b,p,f,t] - tpd[b,p,n,f])
// 4-mic square degeneracy: pairs[3]==pairs[2], pairs[5]==-pairs[0] ->
// rank-8 contraction over 4 distinct phase groups (rep pairs 0,1,2,4):
//   V = uc0*c0 + us0*s0 + uc1*c1 + us1*s1 + uc2*c2 + us2*s2 + uc3*c3 + us3*s3
//
// Round-12: R10's per-thread regime (t-pair, all 36 n per thread -> obs
// sincos once per element, natural regs ~48, no launch_bounds cap) with a
// FINER grid: one block per (b,f), 160 threads, grid=1028. Register limit
// allows 8 blocks/SM; grid supplies 6.9 -> ~35 warps/SM (R10 was grid-
// limited to 3.49 blocks = 17.5 warps). Inner loop per n:
// 2 LDS.128 (broadcast) + 16 FFMA + 1 STG.64.

#define NP    6
#define NG    4
#define NDIR  36
#define NF    257
#define NT    300
#define NB    4
#define NTP   150          // t-pairs

__global__ __launch_bounds__(160)
void dirfeat_kernel(const float* __restrict__ obs,     // (B*P, F, T)
                    const float* __restrict__ azi,     // (B, N)
                    const float* __restrict__ ele,     // (B, N)
                    const float* __restrict__ pairs,   // (P, 3)
                    const float* __restrict__ freq,    // (F,)
                    float* __restrict__ out)           // (B, N, F, T)
{
    const int b  = blockIdx.x / NF;
    const int f  = blockIdx.x - b * NF;
    const int tid = threadIdx.x;

    // cs[n] = {c0,s0,c1,s1, c2,s2,c3,s3}
    __shared__ __align__(16) float cs[NDIR][2 * NG];

    // ---- Phase 1: 144 steering entries, one per thread ----
    if (tid < NDIR * NG) {
        const int n = tid >> 2;
        const int g = tid & 3;
        const int rep = (g == 3) ? 4 : g;   // rep pair indices {0,1,2,4}

        const float a  = azi[b * NDIR + n];
        const float el = ele[b * NDIR + n];
        float sa, ca, se, ce;
        __sincosf(a,  &sa, &ca);
        __sincosf(el, &se, &ce);
        const float rx = se * ca, ry = se * sa, rz = ce;
        const float dot = pairs[rep * 3 + 0] * rx
                        + pairs[rep * 3 + 1] * ry
                        + pairs[rep * 3 + 2] * rz;
        const float tau = (6.283185307179586f / 343.0f) * dot * freq[f];
        float s, c;
        __sincosf(tau, &s, &c);
        cs[n][2 * g]     = c;
        cs[n][2 * g + 1] = s;
    }
    __syncthreads();

    // ---- Phase 2: threads 0..149 -> t-pair; all 36 n per thread ----
    if (tid < NTP) {
        const int t0 = tid * 2;

        const unsigned pstr = NF * NT;                 // 77100
        const float* ob = obs + (unsigned)((b * NP) * NF + f) * NT + t0;

        // Combined obs terms (16 registers)
        float uc0x, uc0y, us0x, us0y;
        float uc1x, uc1y, us1x, us1y;
        float uc2x, uc2y, us2x, us2y;
        float uc3x, uc3y, us3x, us3y;

        {   // group 0: pairs 0 and 5 (negated vector -> sin difference)
            const float2 oA = *reinterpret_cast<const float2*>(ob);
            const float2 oB = *reinterpret_cast<const float2*>(ob + 5 * pstr);
            float sA, cA, sB, cB;
            __sincosf(oA.x, &sA, &cA); __sincosf(oB.x, &sB, &cB);
            uc0x = cA + cB; us0x = sA - sB;
            __sincosf(oA.y, &sA, &cA); __sincosf(oB.y, &sB, &cB);
            uc0y = cA + cB; us0y = sA - sB;
        }
        {   // group 2: pairs 2 and 3 (identical vector -> sum)
            const float2 oA = *reinterpret_cast<const float2*>(ob + 2 * pstr);
            const float2 oB = *reinterpret_cast<const float2*>(ob + 3 * pstr);
            float sA, cA, sB, cB;
            __sincosf(oA.x, &sA, &cA); __sincosf(oB.x, &sB, &cB);
            uc2x = cA + cB; us2x = sA + sB;
            __sincosf(oA.y, &sA, &cA); __sincosf(oB.y, &sB, &cB);
            uc2y = cA + cB; us2y = sA + sB;
        }
        {   // group 1: pair 1 alone
            const float2 o = *reinterpret_cast<const float2*>(ob + 1 * pstr);
            __sincosf(o.x, &us1x, &uc1x);
            __sincosf(o.y, &us1y, &uc1y);
        }
        {   // group 3: pair 4 alone
            const float2 o = *reinterpret_cast<const float2*>(ob + 4 * pstr);
            __sincosf(o.x, &us3x, &uc3x);
            __sincosf(o.y, &us3y, &uc3y);
        }

        const unsigned nstride = NF * NT;
        // Three base pointers keep STG immediate offsets within +/-16MB
        float* outA = out + (unsigned)((b * NDIR) * NF + f) * NT + t0;
        float* outB = outA + 12u * nstride;
        float* outC = outA + 24u * nstride;
        const float4* cp = reinterpret_cast<const float4*>(&cs[0][0]);

#pragma unroll
        for (int i = 0; i < 12; i++) {
#pragma unroll
            for (int k = 0; k < 3; k++) {
                const int n = k * 12 + i;
                const float4 w0 = cp[2 * n];       // c0 s0 c1 s1
                const float4 w1 = cp[2 * n + 1];   // c2 s2 c3 s3

                float a0 = uc0x * w0.x;
                float a1 = uc0y * w0.x;
                a0 = fmaf(us0x, w0.y, a0);  a1 = fmaf(us0y, w0.y, a1);
                a0 = fmaf(uc1x, w0.z, a0);  a1 = fmaf(uc1y, w0.z, a1);
                a0 = fmaf(us1x, w0.w, a0);  a1 = fmaf(us1y, w0.w, a1);
                a0 = fmaf(uc2x, w1.x, a0);  a1 = fmaf(uc2y, w1.x, a1);
                a0 = fmaf(us2x, w1.y, a0);  a1 = fmaf(us2y, w1.y, a1);
                a0 = fmaf(uc3x, w1.z, a0);  a1 = fmaf(uc3y, w1.z, a1);
                a0 = fmaf(us3x, w1.w, a0);  a1 = fmaf(us3y, w1.w, a1);

                float* dst = (k == 0) ? outA : (k == 1) ? outB : outC;
                *reinterpret_cast<float2*>(dst + i * nstride) =
                    make_float2(a0, a1);
            }
        }
    }
}

extern "C" void kernel_launch(void* const* d_in, const int* in_sizes, int n_in,
                              void* d_out, int out_size) {
    const float* obs   = (const float*)d_in[0];
    const float* azi   = (const float*)d_in[1];
    const float* ele   = (const float*)d_in[2];
    const float* pairs = (const float*)d_in[3];
    const float* freq  = (const float*)d_in[4];
    float* out = (float*)d_out;

    dim3 grid(NB * NF);   // 1028 blocks: one per (b,f)
    dim3 block(160);      // 5 warps, 150 active in phase 2
    dirfeat_kernel<<<grid, block>>>(obs, azi, ele, pairs, freq, out);
}